// round 9
// baseline (speedup 1.0000x reference)
#include <cuda_runtime.h>

#define Hc 512
#define Wc 512
#define Bc 8
#define HW (Hc * Wc)
#define HWF2 (HW / 2)   // stride in float2 units

__device__ __forceinline__ float bilin(const float* __restrict__ dep, float py, float px) {
    const float fy = floorf(py);
    const float fx = floorf(px);
    const float ty = py - fy;
    const float tx = px - fx;
    const int y0 = (int)fy;
    const int x0 = (int)fx;

    float v00 = 0.f, v01 = 0.f, v10 = 0.f, v11 = 0.f;
    const int base = y0 * Wc + x0;
    const bool yi0 = (unsigned)y0       < (unsigned)Hc;
    const bool yi1 = (unsigned)(y0 + 1) < (unsigned)Hc;
    const bool xi0 = (unsigned)x0       < (unsigned)Wc;
    const bool xi1 = (unsigned)(x0 + 1) < (unsigned)Wc;
    if (yi0 && xi0) v00 = __ldg(dep + base);
    if (yi0 && xi1) v01 = __ldg(dep + base + 1);
    if (yi1 && xi0) v10 = __ldg(dep + base + Wc);
    if (yi1 && xi1) v11 = __ldg(dep + base + Wc + 1);

    const float top = v00 + (v01 - v00) * tx;
    const float bot = v10 + (v11 - v10) * tx;
    return top + (bot - top) * ty;
}

__global__ __launch_bounds__(256, 2)
void ppd_kernel(const float* __restrict__ depth,
                const float* __restrict__ weight,
                const float* __restrict__ offset,
                float* __restrict__ out)
{
    const int x = blockIdx.x * 64 + threadIdx.x * 2;     // x-pair base (even)
    const int y = blockIdx.y * 8  + threadIdx.y;
    const int b = blockIdx.z;
    const int p = y * Wc + x;

    const float*  __restrict__ dep = depth + (size_t)b * HW;
    const float2* __restrict__ wp  = (const float2*)(weight + (size_t)b * 9  * HW + p);
    const float2* __restrict__ op  = (const float2*)(offset + (size_t)b * 18 * HW + p);

    // ---- load 9 weight-pairs, compute per-pixel mean ----
    float2 w[9];
    float2 mean = make_float2(0.f, 0.f);
#pragma unroll
    for (int k = 0; k < 9; k++) {
        w[k] = __ldg(wp + k * HWF2);
        mean.x += w[k].x;
        mean.y += w[k].y;
    }
    mean.x *= (1.0f / 9.0f);
    mean.y *= (1.0f / 9.0f);

    const float ybase  = (float)(y - 1);
    const float xbase0 = (float)(x - 1);
    const float xbase1 = (float)(x);     // x+1-1

    float2 acc = make_float2(0.f, 0.f);
#pragma unroll
    for (int k = 0; k < 9; k++) {
        const int ky = k / 3;
        const int kx = k % 3;
        const float2 dy2 = __ldg(op + (2 * k)     * HWF2);
        const float2 dx2 = __ldg(op + (2 * k + 1) * HWF2);

        const float pyk = ybase + (float)ky;
        const float s0 = bilin(dep, dy2.x + pyk, dx2.x + xbase0 + (float)kx);
        const float s1 = bilin(dep, dy2.y + pyk, dx2.y + xbase1 + (float)kx);

        acc.x = fmaf(s0, w[k].x - mean.x, acc.x);
        acc.y = fmaf(s1, w[k].y - mean.y, acc.y);
    }

    const float2 d2 = __ldg((const float2*)(dep + p));
    float2 res;
    res.x = acc.x + d2.x;
    res.y = acc.y + d2.y;
    *(float2*)(out + (size_t)b * HW + p) = res;
}

extern "C" void kernel_launch(void* const* d_in, const int* in_sizes, int n_in,
                              void* d_out, int out_size) {
    (void)in_sizes; (void)n_in; (void)out_size;
    const float* depth  = (const float*)d_in[0];
    const float* weight = (const float*)d_in[1];
    const float* offset = (const float*)d_in[2];
    float* out = (float*)d_out;

    dim3 block(32, 8, 1);                       // 256 threads -> 64x8 pixel tile
    dim3 grid(Wc / 64, Hc / 8, Bc);
    ppd_kernel<<<grid, block>>>(depth, weight, offset, out);
}

// round 10
// speedup vs baseline: 1.6241x; 1.6241x over previous
#include <cuda_runtime.h>

#define Hc 512
#define Wc 512
#define Bc 8
#define HW (Hc * Wc)
#define HWF2 (HW / 2)   // stride in float2 units

__device__ __forceinline__ float bilin(const float* __restrict__ dep, float py, float px) {
    const float fy = floorf(py);
    const float fx = floorf(px);
    const float ty = py - fy;
    const float tx = px - fx;
    const int y0 = (int)fy;
    const int x0 = (int)fx;

    float v00 = 0.f, v01 = 0.f, v10 = 0.f, v11 = 0.f;
    const int base = y0 * Wc + x0;
    const bool yi0 = (unsigned)y0       < (unsigned)Hc;
    const bool yi1 = (unsigned)(y0 + 1) < (unsigned)Hc;
    const bool xi0 = (unsigned)x0       < (unsigned)Wc;
    const bool xi1 = (unsigned)(x0 + 1) < (unsigned)Wc;
    if (yi0 && xi0) v00 = __ldg(dep + base);
    if (yi0 && xi1) v01 = __ldg(dep + base + 1);
    if (yi1 && xi0) v10 = __ldg(dep + base + Wc);
    if (yi1 && xi1) v11 = __ldg(dep + base + Wc + 1);

    const float top = v00 + (v01 - v00) * tx;
    const float bot = v10 + (v11 - v10) * tx;
    return top + (bot - top) * ty;
}

__global__ __launch_bounds__(256, 4)
void ppd_kernel(const float* __restrict__ depth,
                const float* __restrict__ weight,
                const float* __restrict__ offset,
                float* __restrict__ out)
{
    const int x = blockIdx.x * 64 + threadIdx.x * 2;     // x-pair base (even)
    const int y = blockIdx.y * 8  + threadIdx.y;
    const int b = blockIdx.z;
    const int p = y * Wc + x;

    const float*  __restrict__ dep = depth + (size_t)b * HW;
    const float2* __restrict__ wp  = (const float2*)(weight + (size_t)b * 9  * HW + p);
    const float2* __restrict__ op  = (const float2*)(offset + (size_t)b * 18 * HW + p);

    const float ybase  = (float)(y - 1);
    const float xbase0 = (float)(x - 1);
    const float xbase1 = (float)(x);     // (x+1) - 1

    // Fused single pass:
    //   out = sum_k s_k*(w_k - mean) + d
    //       = sum_k s_k*w_k  -  (sum_k w_k)/9 * sum_k s_k  + d
    float2 sw    = make_float2(0.f, 0.f);   // sum s*w
    float2 ss    = make_float2(0.f, 0.f);   // sum s
    float2 wsum  = make_float2(0.f, 0.f);   // sum w

#pragma unroll
    for (int k = 0; k < 9; k++) {
        const int ky = k / 3;
        const int kx = k % 3;

        const float2 wk  = __ldg(wp + k * HWF2);
        const float2 dy2 = __ldg(op + (2 * k)     * HWF2);
        const float2 dx2 = __ldg(op + (2 * k + 1) * HWF2);

        const float pyk = ybase + (float)ky;
        const float s0 = bilin(dep, dy2.x + pyk, dx2.x + xbase0 + (float)kx);
        const float s1 = bilin(dep, dy2.y + pyk, dx2.y + xbase1 + (float)kx);

        sw.x   = fmaf(s0, wk.x, sw.x);
        sw.y   = fmaf(s1, wk.y, sw.y);
        ss.x  += s0;
        ss.y  += s1;
        wsum.x += wk.x;
        wsum.y += wk.y;
    }

    const float2 d2 = __ldg((const float2*)(dep + p));
    float2 res;
    res.x = fmaf(-wsum.x * (1.0f / 9.0f), ss.x, sw.x) + d2.x;
    res.y = fmaf(-wsum.y * (1.0f / 9.0f), ss.y, sw.y) + d2.y;
    *(float2*)(out + (size_t)b * HW + p) = res;
}

extern "C" void kernel_launch(void* const* d_in, const int* in_sizes, int n_in,
                              void* d_out, int out_size) {
    (void)in_sizes; (void)n_in; (void)out_size;
    const float* depth  = (const float*)d_in[0];
    const float* weight = (const float*)d_in[1];
    const float* offset = (const float*)d_in[2];
    float* out = (float*)d_out;

    dim3 block(32, 8, 1);                       // 256 threads -> 64x8 pixel tile
    dim3 grid(Wc / 64, Hc / 8, Bc);
    ppd_kernel<<<grid, block>>>(depth, weight, offset, out);
}